// round 13
// baseline (speedup 1.0000x reference)
#include <cuda_runtime.h>
#include <cstdint>

#define FULL 0xffffffffu
typedef unsigned long long u64;

// ---- packed f32x2 helpers (Blackwell FFMA2 — only reachable via PTX) ----
__device__ __forceinline__ u64 pk2(float lo, float hi) {
    u64 r;
    asm("mov.b64 %0, {%1, %2};" : "=l"(r) : "f"(lo), "f"(hi));
    return r;
}
__device__ __forceinline__ float2 upk2(u64 p) {
    float2 v;
    asm("mov.b64 {%0, %1}, %2;" : "=f"(v.x), "=f"(v.y) : "l"(p));
    return v;
}
__device__ __forceinline__ u64 fma2(u64 a, u64 b, u64 c) {
    u64 d;
    asm("fma.rn.f32x2 %0, %1, %2, %3;" : "=l"(d) : "l"(a), "l"(b), "l"(c));
    return d;
}
__device__ __forceinline__ u64 mul2(u64 a, u64 b) {
    u64 d;
    asm("mul.rn.f32x2 %0, %1, %2;" : "=l"(d) : "l"(a), "l"(b), "l"(b));
    return d;
}

// Fused split-K kernel, 8 rows per 256-thread block, ZERO shuffles in phase 1.
// Partials array P[t][68] (stride 68 words: 16B-aligned, bank-conflict-free for
// STS.128 at 272B lane stride and for coalesced stage-A LDS.32).
// Phase 1: thread t owns j in [t*4, t*4+4); W1 slice (8 qubits x 4 j) reg-resident.
//   Per row: 1 LDG.128 (x), 16 FFMA2, 8 FADD folds, 2 STS.128 -> P[t][r*8..r*8+7].
// Stage A (all 256 threads): thread (idx=tid&63, c=tid>>6) sums P[64c..64c+63][idx]
//   with 64 coalesced LDS.32 -> smem2[c][idx].
// Quantum (threads 0..63): a = sum_c smem2[c][idx] + b1; closed-form
//   z = cos(th)cos(a) - sin(th)sin(phi)sin(a); CNOT ring conjugated to Z-strings
//   -> qout[0]=z1..z7, qout[i]=z0..zi via octet prefix products (only SHFLs left).
// Phase 2 (R6 layout): e = wid*128 + c*32 + lane; W2 reg-resident (preloaded while
//   W1 regs die); bias folded; per row 2 broadcast LDS + 16 FFMA2 + 4 STG.32.
__global__ void __launch_bounds__(256, 3)
ffq_kernel(const float* __restrict__ x,  const float* __restrict__ W1,
           const float* __restrict__ b1, const float* __restrict__ qp,
           const float* __restrict__ W2, const float* __restrict__ b2,
           float* __restrict__ out, int nrows)
{
    extern __shared__ float P[];                 // [256][68] partials (69.6 KB)
    __shared__ __align__(16) float smem2[4][64]; // stage-A chunk sums
    __shared__ __align__(16) float sq[8][8];     // qout per row

    const int tid  = threadIdx.x;
    const int lane = tid & 31;
    const int wid  = tid >> 5;
    const int rowblk = blockIdx.x * 8;

    const int j0 = tid * 4;                      // this thread's 4 j's

    // ---------------- Phase 1: W1 reg-resident, no shuffles ----------------
    u64 wp0[8], wp1[8];
#pragma unroll
    for (int i = 0; i < 8; i++) {
        longlong2 w = __ldg((const longlong2*)(W1 + (size_t)i * 1024 + j0));
        wp0[i] = (u64)w.x;
        wp1[i] = (u64)w.y;
    }

    float* Pt = P + tid * 68;

#pragma unroll 4
    for (int rloc = 0; rloc < 8; rloc++) {
        const int row = min(rowblk + rloc, nrows - 1);
        longlong2 xv = __ldg((const longlong2*)(x + (size_t)row * 1024 + j0));
        const u64 x0 = (u64)xv.x, x1 = (u64)xv.y;

        float v[8];
#pragma unroll
        for (int i = 0; i < 8; i++) {
            u64 s = mul2(x0, wp0[i]);
            s = fma2(x1, wp1[i], s);
            float2 f = upk2(s);
            v[i] = f.x + f.y;
        }
        // 2 conflict-free STS.128: P[tid][rloc*8 .. rloc*8+7]
        *((float4*)(Pt + rloc * 8))     = make_float4(v[0], v[1], v[2], v[3]);
        *((float4*)(Pt + rloc * 8 + 4)) = make_float4(v[4], v[5], v[6], v[7]);
    }

    // ---- Phase 2 weights: load now (W1 regs dead; latency hides behind stage A) ----
    u64 w2r[4][4];
    u64 bvp[4];
#pragma unroll
    for (int c = 0; c < 4; c++) {
        const int e = wid * 128 + c * 32 + lane;
        longlong2 a = __ldg((const longlong2*)(W2 + (size_t)e * 8));
        longlong2 b = __ldg((const longlong2*)(W2 + (size_t)e * 8 + 4));
        w2r[c][0] = (u64)a.x;
        w2r[c][1] = (u64)a.y;
        w2r[c][2] = (u64)b.x;
        w2r[c][3] = (u64)b.y;
        bvp[c] = pk2(__ldg(b2 + e), 0.0f);
    }
    __syncthreads();

    // ---------------- Stage A: distributed reduction over t ----------------
    {
        const int idx = tid & 63;      // r*8 + q
        const int c   = tid >> 6;      // t-chunk
        const float* pc = P + c * 64 * 68 + idx;
        float a0 = 0.f, a1 = 0.f, a2 = 0.f, a3 = 0.f;
#pragma unroll 4
        for (int t = 0; t < 64; t += 4) {
            a0 += pc[(t + 0) * 68];
            a1 += pc[(t + 1) * 68];
            a2 += pc[(t + 2) * 68];
            a3 += pc[(t + 3) * 68];
        }
        smem2[c][idx] = (a0 + a1) + (a2 + a3);
    }
    __syncthreads();

    // ---------------- Quantum: one thread per (row, qubit) ----------------
    if (tid < 64) {
        const int qi = tid & 7;

        const float a = ((smem2[0][tid] + smem2[1][tid])
                      +  (smem2[2][tid] + smem2[3][tid])) + __ldg(b1 + qi);

        const float phi   = __ldg(qp + 3 * qi);
        const float theta = __ldg(qp + 3 * qi + 1);
        const float k1 = cosf(theta);
        const float k2 = sinf(theta) * sinf(phi);

        float sa, ca;
        __sincosf(a, &sa, &ca);
        const float z = k1 * ca - k2 * sa;

        // inclusive prefix product over each 8-lane octet
        float p = z;
#pragma unroll
        for (int d = 1; d < 8; d <<= 1) {
            float t = __shfl_up_sync(FULL, p, d, 8);
            if (qi >= d) p *= t;
        }
        // second scan with z0 -> 1 for qout[0] = z1..z7
        float wv = (qi == 0) ? 1.0f : z;
#pragma unroll
        for (int d = 1; d < 8; d <<= 1) {
            float t = __shfl_up_sync(FULL, wv, d, 8);
            if (qi >= d) wv *= t;
        }
        const float pb7 = __shfl_sync(FULL, wv, 7, 8);
        sq[tid >> 3][qi] = (qi == 0) ? pb7 : p;
    }
    __syncthreads();

    // ---------------- Phase 2: GEMM2, W2 reg-resident, bias folded ----------------
#pragma unroll 4
    for (int rloc = 0; rloc < 8; rloc++) {
        const int row = rowblk + rloc;
        if (row >= nrows) break;

        const longlong2* sp = (const longlong2*)sq[rloc];   // broadcast LDS x2
        longlong2 qa = sp[0], qb = sp[1];
        const u64 qd0 = (u64)qa.x, qd1 = (u64)qa.y;
        const u64 qd2 = (u64)qb.x, qd3 = (u64)qb.y;

        float* orow = out + (size_t)row * 1024 + wid * 128 + lane;
#pragma unroll
        for (int c = 0; c < 4; c++) {
            u64 s = fma2(w2r[c][0], qd0, bvp[c]);
            s = fma2(w2r[c][1], qd1, s);
            s = fma2(w2r[c][2], qd2, s);
            s = fma2(w2r[c][3], qd3, s);
            float2 f = upk2(s);
            orow[c * 32] = f.x + f.y;
        }
    }
}

extern "C" void kernel_launch(void* const* d_in, const int* in_sizes, int n_in,
                              void* d_out, int out_size)
{
    const float* x  = (const float*)d_in[0];
    const float* W1 = (const float*)d_in[1];
    const float* b1 = (const float*)d_in[2];
    const float* qp = (const float*)d_in[3];
    const float* W2 = (const float*)d_in[4];
    const float* b2 = (const float*)d_in[5];
    float* out = (float*)d_out;

    const int nrows = in_sizes[0] / 1024;            // batch * seq_len
    const int nblocks = (nrows + 7) / 8;             // 8 rows per block
    const int smem_bytes = 256 * 68 * sizeof(float); // 69,632 B

    static int configured = 0;
    if (!configured) {
        cudaFuncSetAttribute(ffq_kernel,
                             cudaFuncAttributeMaxDynamicSharedMemorySize,
                             smem_bytes);
        configured = 1;
    }

    ffq_kernel<<<nblocks, 256, smem_bytes>>>(x, W1, b1, qp, W2, b2, out, nrows);
}